// round 1
// baseline (speedup 1.0000x reference)
#include <cuda_runtime.h>

#define NN 100000
#define MM 1000
#define KK 12
#define TPB 256
#define VN 4     // n-values per thread (float4 store)
#define MC 250   // m-values per block

// Scratch (no cudaMalloc allowed)
__device__ float g_A[(size_t)NN * KK];  // per-n features, AoS 12 floats
__device__ float g_B[(size_t)MM * KK];  // per-m features, AoS 12 floats

typedef unsigned long long u64;

__device__ __forceinline__ u64 pack2(float lo, float hi) {
    u64 r; asm("mov.b64 %0, {%1,%2};" : "=l"(r) : "f"(lo), "f"(hi)); return r;
}
__device__ __forceinline__ void unpack2(u64 v, float& lo, float& hi) {
    asm("mov.b64 {%0,%1}, %2;" : "=f"(lo), "=f"(hi) : "l"(v));
}
__device__ __forceinline__ u64 fma2(u64 a, u64 b, u64 c) {
    u64 d; asm("fma.rn.f32x2 %0, %1, %2, %3;" : "=l"(d) : "l"(a), "l"(b), "l"(c)); return d;
}
__device__ __forceinline__ u64 add2(u64 a, u64 b) {
    u64 d; asm("add.rn.f32x2 %0, %1, %2;" : "=l"(d) : "l"(a), "l"(b)); return d;
}

// Per-n features: y0,y1 = phi[r,n]*POD[n,r]; pool terms scaled by c; sin/cos/tanh terms.
// Also writes latent_spatial (N,2) output block.
__global__ void prep_A(const float* __restrict__ phi, const float* __restrict__ POD,
                       const float* __restrict__ c, const float* __restrict__ omega,
                       float* __restrict__ out_latent) {
    int n = blockIdx.x * blockDim.x + threadIdx.x;
    if (n >= NN) return;
    float y0 = phi[n]      * POD[2 * n];
    float y1 = phi[NN + n] * POD[2 * n + 1];
    float* a = g_A + (size_t)n * KK;
    a[0]  = c[0];
    a[1]  = c[1] * y0;
    a[2]  = c[2] * y1;
    a[3]  = c[3] * y0 * y0;
    a[4]  = c[4] * y0 * y1;
    a[5]  = c[5] * y1 * y1;
    a[6]  = sinf(omega[0] * y0);   // omega[0::3] = {omega[0], omega[3]}
    a[7]  = sinf(omega[3] * y1);
    a[8]  = cosf(omega[1] * y0);   // omega[1::3] = {omega[1], omega[4]}
    a[9]  = cosf(omega[4] * y1);
    a[10] = tanhf(omega[2] * y0);  // omega[2::3] = {omega[2], omega[5]}
    a[11] = tanhf(omega[5] * y1);
    out_latent[2 * n]     = y0;
    out_latent[2 * n + 1] = y1;
}

// Per-m features; also copies z_values (6,M) into the output tail.
__global__ void prep_B(const float* __restrict__ z, const float* __restrict__ zsin,
                       const float* __restrict__ zcos, const float* __restrict__ ztanh,
                       const float* __restrict__ sc, const float* __restrict__ cc,
                       const float* __restrict__ tc, float* __restrict__ out_z) {
    int m = blockIdx.x * blockDim.x + threadIdx.x;
    if (m >= MM) return;
    float* b = g_B + (size_t)m * KK;
#pragma unroll
    for (int t = 0; t < 6; t++) {
        float v = z[t * MM + m];
        b[t] = v;
        out_z[t * MM + m] = v;
    }
    b[6]  = sc[0] * zsin[m];        b[7]  = sc[1] * zsin[MM + m];
    b[8]  = cc[0] * zcos[m];        b[9]  = cc[1] * zcos[MM + m];
    b[10] = tc[0] * ztanh[m];       b[11] = tc[1] * ztanh[MM + m];
}

// Rank-12 outer product: out[m*N + n] = dot12(A[n], B[m]).
// Block: 256 threads x 4 n each (1024 contiguous n), 250 m per block (shared-cached).
__global__ void __launch_bounds__(TPB)
main_kernel(float* __restrict__ out) {
    __shared__ u64 Bs[MC * KK];  // B row values duplicated into both f32x2 lanes

    int mBase = blockIdx.y * MC;
    for (int i = threadIdx.x; i < MC * KK; i += TPB) {
        float v = g_B[(size_t)mBase * KK + i];
        Bs[i] = pack2(v, v);
    }
    __syncthreads();

    int n0 = (blockIdx.x * TPB + threadIdx.x) * VN;
    if (n0 >= NN) return;   // N % 4 == 0, so in-range threads always write full float4

    // Load 4 A rows (12 floats each) via float4, then pack as f32x2 pairs across n.
    const float4* ap = (const float4*)(g_A + (size_t)n0 * KK);
    float av[VN][KK];
#pragma unroll
    for (int j = 0; j < VN; j++) {
#pragma unroll
        for (int q = 0; q < 3; q++) {
            float4 f = ap[j * 3 + q];
            av[j][q * 4 + 0] = f.x; av[j][q * 4 + 1] = f.y;
            av[j][q * 4 + 2] = f.z; av[j][q * 4 + 3] = f.w;
        }
    }
    u64 pa01[KK], pa23[KK];
#pragma unroll
    for (int k = 0; k < KK; k++) {
        pa01[k] = pack2(av[0][k], av[1][k]);
        pa23[k] = pack2(av[2][k], av[3][k]);
    }

    float* outBase = out + (size_t)mBase * NN + n0;
#pragma unroll 2
    for (int mi = 0; mi < MC; ++mi) {
        const u64* bb = Bs + mi * KK;
        u64 acc01a = 0ull, acc01b = 0ull, acc23a = 0ull, acc23b = 0ull;
#pragma unroll
        for (int k = 0; k < KK; k += 2) {
            u64 b0 = bb[k], b1 = bb[k + 1];
            acc01a = fma2(pa01[k],     b0, acc01a);
            acc01b = fma2(pa01[k + 1], b1, acc01b);
            acc23a = fma2(pa23[k],     b0, acc23a);
            acc23b = fma2(pa23[k + 1], b1, acc23b);
        }
        u64 acc01 = add2(acc01a, acc01b);
        u64 acc23 = add2(acc23a, acc23b);
        float4 o;
        unpack2(acc01, o.x, o.y);
        unpack2(acc23, o.z, o.w);
        *(float4*)(outBase + (size_t)mi * NN) = o;
    }
}

extern "C" void kernel_launch(void* const* d_in, const int* in_sizes, int n_in,
                              void* d_out, int out_size) {
    // Input order (metadata): X, phi, POD_modes, c_coef, z_values, zsin, zcos,
    //                         ztanh, sin_coef, cos_coef, tanh_coef, omega
    const float* phi   = (const float*)d_in[1];
    const float* POD   = (const float*)d_in[2];
    const float* c     = (const float*)d_in[3];
    const float* z     = (const float*)d_in[4];
    const float* zsin  = (const float*)d_in[5];
    const float* zcos  = (const float*)d_in[6];
    const float* ztanh = (const float*)d_in[7];
    const float* sc    = (const float*)d_in[8];
    const float* cc    = (const float*)d_in[9];
    const float* tc    = (const float*)d_in[10];
    const float* omega = (const float*)d_in[11];

    float* out        = (float*)d_out;
    float* out_final  = out;                              // (M, N) = final_reconstruction.T
    float* out_latent = out + (size_t)MM * NN;            // (N, 2) = latent_spatial
    float* out_z      = out_latent + (size_t)NN * 2;      // (6, M) = z_values

    prep_A<<<(NN + 255) / 256, 256>>>(phi, POD, c, omega, out_latent);
    prep_B<<<(MM + 255) / 256, 256>>>(z, zsin, zcos, ztanh, sc, cc, tc, out_z);

    dim3 grid((NN / VN + TPB - 1) / TPB, MM / MC);  // (98, 4)
    main_kernel<<<grid, TPB>>>(out_final);
}

// round 2
// speedup vs baseline: 1.1051x; 1.1051x over previous
#include <cuda_runtime.h>

#define NN 100000
#define MM 1000
#define KK 12
#define TPB 256
#define VN 4     // n-values per thread (float4 store)
#define MC 250   // m-values per block

// Scratch (no cudaMalloc allowed)
__device__ float g_A[(size_t)KK * NN];  // per-n features, SoA: g_A[k*NN + n]
__device__ float g_B[(size_t)MM * KK];  // per-m features, AoS 12 floats

typedef unsigned long long u64;

__device__ __forceinline__ u64 pack2(float lo, float hi) {
    u64 r; asm("mov.b64 %0, {%1,%2};" : "=l"(r) : "f"(lo), "f"(hi)); return r;
}
__device__ __forceinline__ void unpack2(u64 v, float& lo, float& hi) {
    asm("mov.b64 {%0,%1}, %2;" : "=f"(lo), "=f"(hi) : "l"(v));
}
__device__ __forceinline__ u64 fma2(u64 a, u64 b, u64 c) {
    u64 d; asm("fma.rn.f32x2 %0, %1, %2, %3;" : "=l"(d) : "l"(a), "l"(b), "l"(c)); return d;
}
__device__ __forceinline__ float fast_sin(float x)  { float r; asm("sin.approx.f32 %0, %1;"  : "=f"(r) : "f"(x)); return r; }
__device__ __forceinline__ float fast_cos(float x)  { float r; asm("cos.approx.f32 %0, %1;"  : "=f"(r) : "f"(x)); return r; }
__device__ __forceinline__ float fast_tanh(float x) { float r; asm("tanh.approx.f32 %0, %1;" : "=f"(r) : "f"(x)); return r; }

// Per-n features in SoA layout (coalesced stores) using MUFU approx transcendentals.
// Also writes latent_spatial (N,2) output block.
__global__ void prep_A(const float* __restrict__ phi, const float* __restrict__ POD,
                       const float* __restrict__ c, const float* __restrict__ omega,
                       float* __restrict__ out_latent) {
    int n = blockIdx.x * blockDim.x + threadIdx.x;
    if (n >= NN) return;
    float y0 = phi[n]      * POD[2 * n];
    float y1 = phi[NN + n] * POD[2 * n + 1];
    g_A[0 * NN + n]  = c[0];
    g_A[1 * NN + n]  = c[1] * y0;
    g_A[2 * NN + n]  = c[2] * y1;
    g_A[3 * NN + n]  = c[3] * y0 * y0;
    g_A[4 * NN + n]  = c[4] * y0 * y1;
    g_A[5 * NN + n]  = c[5] * y1 * y1;
    g_A[6 * NN + n]  = fast_sin(omega[0] * y0);   // omega[0::3] = {omega[0], omega[3]}
    g_A[7 * NN + n]  = fast_sin(omega[3] * y1);
    g_A[8 * NN + n]  = fast_cos(omega[1] * y0);   // omega[1::3] = {omega[1], omega[4]}
    g_A[9 * NN + n]  = fast_cos(omega[4] * y1);
    g_A[10 * NN + n] = fast_tanh(omega[2] * y0);  // omega[2::3] = {omega[2], omega[5]}
    g_A[11 * NN + n] = fast_tanh(omega[5] * y1);
    out_latent[2 * n]     = y0;
    out_latent[2 * n + 1] = y1;
}

// Per-m features; also copies z_values (6,M) into the output tail.
__global__ void prep_B(const float* __restrict__ z, const float* __restrict__ zsin,
                       const float* __restrict__ zcos, const float* __restrict__ ztanh,
                       const float* __restrict__ sc, const float* __restrict__ cc,
                       const float* __restrict__ tc, float* __restrict__ out_z) {
    int m = blockIdx.x * blockDim.x + threadIdx.x;
    if (m >= MM) return;
    float* b = g_B + (size_t)m * KK;
#pragma unroll
    for (int t = 0; t < 6; t++) {
        float v = z[t * MM + m];
        b[t] = v;
        out_z[t * MM + m] = v;
    }
    b[6]  = sc[0] * zsin[m];        b[7]  = sc[1] * zsin[MM + m];
    b[8]  = cc[0] * zcos[m];        b[9]  = cc[1] * zcos[MM + m];
    b[10] = tc[0] * ztanh[m];       b[11] = tc[1] * ztanh[MM + m];
}

// Rank-12 outer product: out[m*N + n] = dot12(A[n], B[m]).
// Block: 256 threads x 4 n each (1024 contiguous n), 250 m per block (shared-cached).
__global__ void __launch_bounds__(TPB)
main_kernel(float* __restrict__ out) {
    __shared__ __align__(16) u64 Bs[MC * KK];  // B duplicated into both f32x2 lanes

    int mBase = blockIdx.y * MC;
    for (int i = threadIdx.x; i < MC * KK; i += TPB) {
        float v = g_B[(size_t)mBase * KK + i];
        Bs[i] = pack2(v, v);
    }
    __syncthreads();

    int n0 = (blockIdx.x * TPB + threadIdx.x) * VN;
    if (n0 >= NN) return;   // NN % 4 == 0 -> in-range threads write full float4

    // Load A columns (SoA, coalesced float4 across 4 n's) and pack as f32x2 pairs.
    u64 pa01[KK], pa23[KK];
#pragma unroll
    for (int k = 0; k < KK; k++) {
        float4 f = *(const float4*)(g_A + (size_t)k * NN + n0);
        pa01[k] = pack2(f.x, f.y);
        pa23[k] = pack2(f.z, f.w);
    }

    float* outBase = out + (size_t)mBase * NN + n0;
#pragma unroll 2
    for (int mi = 0; mi < MC; ++mi) {
        const ulonglong2* bb = (const ulonglong2*)(Bs + mi * KK);  // 6x LDS.128
        u64 acc01 = 0ull, acc23 = 0ull;
#pragma unroll
        for (int kk = 0; kk < KK / 2; kk++) {
            ulonglong2 b = bb[kk];
            acc01 = fma2(pa01[2 * kk],     b.x, acc01);
            acc23 = fma2(pa23[2 * kk],     b.x, acc23);
            acc01 = fma2(pa01[2 * kk + 1], b.y, acc01);
            acc23 = fma2(pa23[2 * kk + 1], b.y, acc23);
        }
        float4 o;
        unpack2(acc01, o.x, o.y);
        unpack2(acc23, o.z, o.w);
        // Streaming store: evict-first in L2, output never re-read.
        asm volatile("st.global.cs.v4.f32 [%0], {%1,%2,%3,%4};"
                     :: "l"(outBase + (size_t)mi * NN),
                        "f"(o.x), "f"(o.y), "f"(o.z), "f"(o.w) : "memory");
    }
}

extern "C" void kernel_launch(void* const* d_in, const int* in_sizes, int n_in,
                              void* d_out, int out_size) {
    // Input order: X, phi, POD_modes, c_coef, z_values, zsin, zcos,
    //              ztanh, sin_coef, cos_coef, tanh_coef, omega
    const float* phi   = (const float*)d_in[1];
    const float* POD   = (const float*)d_in[2];
    const float* c     = (const float*)d_in[3];
    const float* z     = (const float*)d_in[4];
    const float* zsin  = (const float*)d_in[5];
    const float* zcos  = (const float*)d_in[6];
    const float* ztanh = (const float*)d_in[7];
    const float* sc    = (const float*)d_in[8];
    const float* cc    = (const float*)d_in[9];
    const float* tc    = (const float*)d_in[10];
    const float* omega = (const float*)d_in[11];

    float* out        = (float*)d_out;
    float* out_final  = out;                              // (M, N) = final_reconstruction.T
    float* out_latent = out + (size_t)MM * NN;            // (N, 2) = latent_spatial
    float* out_z      = out_latent + (size_t)NN * 2;      // (6, M) = z_values

    prep_A<<<(NN + 255) / 256, 256>>>(phi, POD, c, omega, out_latent);
    prep_B<<<(MM + 255) / 256, 256>>>(z, zsin, zcos, ztanh, sc, cc, tc, out_z);

    dim3 grid((NN / VN + TPB - 1) / TPB, MM / MC);  // (98, 4)
    main_kernel<<<grid, TPB>>>(out_final);
}